// round 8
// baseline (speedup 1.0000x reference)
#include <cuda_runtime.h>
#include <math.h>

#define NTOT 8192
#define DD   128
#define EMBD 64

// ---------------- scratch (device globals; no allocations) ----------------
__device__ float g_A [NTOT*DD];
__device__ float g_P [2][NTOT*DD];     // K-split partials of L@x
__device__ float g_B [2][NTOT*DD];
__device__ float g_Dk[2][NTOT*EMBD];
__device__ float g_E [2][NTOT*EMBD];
__device__ float g_Z [NTOT*EMBD];
__device__ int   g_cnt[NTOT];

// transposed bf16 hi/lo operands (X^T layouts [C][NTOT], K-contiguous)
__device__ unsigned short g_xt_hi [DD*NTOT];
__device__ unsigned short g_xt_lo [DD*NTOT];
__device__ unsigned short g_act_hi[DD*NTOT];
__device__ unsigned short g_act_lo[DD*NTOT];
__device__ unsigned short g_dt_hi [2][EMBD*NTOT];
__device__ unsigned short g_dt_lo [2][EMBD*NTOT];

// ---------------- helpers ----------------
__device__ __forceinline__ unsigned smem_u32(const void* p) {
    unsigned a;
    asm("{ .reg .u64 t; cvta.to.shared.u64 t, %1; cvt.u32.u64 %0, t; }" : "=r"(a) : "l"(p));
    return a;
}
#define SWZ(o) ((o) ^ (((o) >> 3) & 0x70))

#define LDSM4(d0,d1,d2,d3,addr) \
    asm volatile("ldmatrix.sync.aligned.m8n8.x4.shared.b16 {%0,%1,%2,%3}, [%4];" \
        : "=r"(d0), "=r"(d1), "=r"(d2), "=r"(d3) : "r"(addr))

#define MMA16816(c, a, b) \
    asm volatile("mma.sync.aligned.m16n8k16.row.col.f32.bf16.bf16.f32 " \
        "{%0,%1,%2,%3},{%4,%5,%6,%7},{%8,%9},{%0,%1,%2,%3};" \
        : "+f"((c)[0]), "+f"((c)[1]), "+f"((c)[2]), "+f"((c)[3]) \
        : "r"((a)[0]), "r"((a)[1]), "r"((a)[2]), "r"((a)[3]), \
          "r"((b)[0]), "r"((b)[1]))

#define CP16(dst, src) \
    asm volatile("cp.async.cg.shared.global [%0], [%1], 16;" :: "r"(dst), "l"(src))
#define CP_COMMIT() asm volatile("cp.async.commit_group;" ::: "memory")
#define CP_WAIT0()  asm volatile("cp.async.wait_group 0;" ::: "memory")

// bf16 hi/lo split of a float pair: hi = truncation (PRMT), lo = rn(x - hi)
__device__ __forceinline__ void split2(float f0, float f1, unsigned& hi, unsigned& lo) {
    unsigned u0 = __float_as_uint(f0), u1 = __float_as_uint(f1);
    unsigned h;
    asm("prmt.b32 %0, %1, %2, 0x7632;" : "=r"(h) : "r"(u0), "r"(u1));
    float h0 = __uint_as_float(u0 & 0xFFFF0000u);
    float h1 = __uint_as_float(u1 & 0xFFFF0000u);
    float r0 = f0 - h0, r1 = f1 - h1;
    unsigned l;
    asm("cvt.rn.bf16x2.f32 %0, %1, %2;" : "=r"(l) : "f"(r1), "f"(r0));
    hi = h; lo = l;
}

// ---------------- tiny kernels ----------------
__global__ void zero_cnt_kernel() {
    g_cnt[blockIdx.x*blockDim.x + threadIdx.x] = 0;
}
__global__ void count_kernel(const int* __restrict__ n_id) {
    atomicAdd(&g_cnt[n_id[blockIdx.x*blockDim.x + threadIdx.x]], 1);
}

// ---------------- transpose + bf16-split: [NTOT][C] f32 -> [C][NTOT] hi/lo ----
// SRC: 0=x(param) 2=g_Dk[0] 3=g_Dk[1]
template<int C, int SRC>
__global__ __launch_bounds__(256) void tsplit(const float* __restrict__ xext)
{
    const float* in;
    unsigned short *hi, *lo;
    if (SRC == 0)      { in = xext;    hi = g_xt_hi;    lo = g_xt_lo; }
    else if (SRC == 2) { in = g_Dk[0]; hi = g_dt_hi[0]; lo = g_dt_lo[0]; }
    else               { in = g_Dk[1]; hi = g_dt_hi[1]; lo = g_dt_lo[1]; }

    __shared__ float tile[64][C + 4];
    const int t  = threadIdx.x;
    const int r0 = blockIdx.x * 64;
    constexpr int F4 = C / 4;
    #pragma unroll
    for (int i = 0; i < 64*F4/256; i++) {
        int u = t + i*256;
        int row = u / F4, c4 = u % F4;
        float4 v = *(const float4*)&in[(size_t)(r0+row)*C + c4*4];
        tile[row][c4*4+0] = v.x; tile[row][c4*4+1] = v.y;
        tile[row][c4*4+2] = v.z; tile[row][c4*4+3] = v.w;
    }
    __syncthreads();
    const int c = t % C, grp = t / C;
    constexpr int RP = 64 / (256 / C);
    #pragma unroll
    for (int i = 0; i < RP/2; i++) {
        int r = grp*RP + 2*i;
        unsigned h, l;
        split2(tile[r][c], tile[r+1][c], h, l);
        *(unsigned*)&hi[(size_t)c*NTOT + r0 + r] = h;
        *(unsigned*)&lo[(size_t)c*NTOT + r0 + r] = l;
    }
}

// ---- fused: A = x - tau*(P0+P1); write g_A; transpose-split cnt*A -> act ----
__global__ __launch_bounds__(256) void combine_tsplit(const float* __restrict__ x,
                                                      const float* __restrict__ taup)
{
    __shared__ float tile[64][DD + 4];
    const int t  = threadIdx.x;
    const int r0 = blockIdx.x * 64;
    const float tv = taup[0];
    #pragma unroll
    for (int i = 0; i < 8; i++) {
        int u = t + i*256;
        int row = u >> 5, c4 = u & 31;
        size_t o = (size_t)(r0+row)*DD + c4*4;
        float4 xv = *(const float4*)&x[o];
        float4 p0 = *(const float4*)&g_P[0][o];
        float4 p1 = *(const float4*)&g_P[1][o];
        float cn = (float)g_cnt[r0+row];
        float4 a;
        a.x = xv.x - tv*(p0.x + p1.x);
        a.y = xv.y - tv*(p0.y + p1.y);
        a.z = xv.z - tv*(p0.z + p1.z);
        a.w = xv.w - tv*(p0.w + p1.w);
        *(float4*)&g_A[o] = a;
        tile[row][c4*4+0] = cn*a.x; tile[row][c4*4+1] = cn*a.y;
        tile[row][c4*4+2] = cn*a.z; tile[row][c4*4+3] = cn*a.w;
    }
    __syncthreads();
    const int c = t & 127, grp = t >> 7;     // 2 groups of 128 threads
    #pragma unroll
    for (int i = 0; i < 16; i++) {           // 32 rows per group, 2 per iter
        int r = grp*32 + 2*i;
        unsigned h, l;
        split2(tile[r][c], tile[r+1][c], h, l);
        *(unsigned*)&g_act_hi[(size_t)c*NTOT + r0 + r] = h;
        *(unsigned*)&g_act_lo[(size_t)c*NTOT + r0 + r] = l;
    }
}

// ---------------- HMMA GEMM: 64-row tiles, 2 CTAs/SM ----------------
// MODE 0: Mat=L, K-split y  -> g_P[y]  (NB=128, grid(128,2))
// MODE 1: Mat=K[y], X=Ac^T  -> g_B[y]  (NB=128, grid(128,2))
// MODE 2: Mat=K[y], X=Dk^T  -> g_E[y]  (NB=64,  grid(128,2))
template<int NB, int MODE>
__global__ __launch_bounds__(256, 2) void gemm_hmma(const float* __restrict__ Mb)
{
    extern __shared__ char smem[];
    constexpr int NF  = NB / 16;        // n-frags per warp (warp covers NB/2 cols)
    constexpr int XSZ = NB * 128;       // bytes per X half-tile, 128B rows
    constexpr int XU  = NB / 32;        // 16B cp.async per thread per X half
    constexpr int NC  = (MODE == 0) ? 64 : 128;

    const int t = threadIdx.x, lane = t & 31, w = t >> 5;
    const int wm = w & 3, wn = w >> 2;
    const int r0 = blockIdx.x * 64;
    const int y  = blockIdx.y;
    const int kbase = (MODE == 0) ? (y << 12) : 0;

    const float* Mat = (MODE == 0) ? Mb : Mb + (size_t)y * NTOT * NTOT;
    const unsigned short *XH, *XL;
    if (MODE == 0)      { XH = g_xt_hi;    XL = g_xt_lo; }
    else if (MODE == 1) { XH = g_act_hi;   XL = g_act_lo; }
    else                { XH = g_dt_hi[y]; XL = g_dt_lo[y]; }

    const unsigned su = smem_u32(smem);
    // layout: stage s: A hi @ s*16384, A lo @ s*16384+8192 ; X @ 32768 + s*2*XSZ

    float acc[NF][4];
    #pragma unroll
    for (int nf = 0; nf < NF; nf++)
        #pragma unroll
        for (int j = 0; j < 4; j++) acc[nf][j] = 0.f;

    float4 mv[4];

    auto LOADG = [&](int c) {
        const int k0 = kbase + c * 64;
        const int s  = c & 1;
        #pragma unroll
        for (int i = 0; i < 4; i++) {
            int u = t + (i << 8);
            mv[i] = *(const float4*)&Mat[(size_t)(r0 + (u >> 4))*NTOT + k0 + ((u & 15) << 2)];
        }
        const unsigned xHb = su + 32768 + s*2*XSZ;
        #pragma unroll
        for (int i = 0; i < XU; i++) {
            int u = t + (i << 8);
            unsigned off = SWZ((unsigned)((u >> 3)*128 + (u & 7)*16));
            size_t  o = (size_t)(u >> 3)*NTOT + k0 + ((u & 7) << 3);
            CP16(xHb + off,       (const void*)&XH[o]);
            CP16(xHb + XSZ + off, (const void*)&XL[o]);
        }
        CP_COMMIT();
    };

    LOADG(0);
    for (int c = 0; c < NC; c++) {
        const int s = c & 1;
        char* aH = smem + s*16384;
        char* aL = aH + 8192;
        // store Mat tile (fp32 -> bf16 hi/lo, swizzled 128B rows)
        #pragma unroll
        for (int i = 0; i < 4; i++) {
            int u = t + (i << 8);
            int row = u >> 4, c4 = u & 15;
            unsigned h0, l0, h1, l1;
            split2(mv[i].x, mv[i].y, h0, l0);
            split2(mv[i].z, mv[i].w, h1, l1);
            unsigned off = SWZ((unsigned)(row*128 + c4*8));
            *(uint2*)(aH + off) = make_uint2(h0, h1);
            *(uint2*)(aL + off) = make_uint2(l0, l1);
        }
        CP_WAIT0();
        __syncthreads();

        if (c + 1 < NC) LOADG(c + 1);

        const unsigned aHb = su + s*16384;
        const unsigned aLb = aHb + 8192;
        const unsigned xHb = su + 32768 + s*2*XSZ;
        const unsigned xLb = xHb + XSZ;

        #pragma unroll
        for (int kk = 0; kk < 4; kk++) {
            const int kc2 = kk * 32;
            unsigned ah[4], al[4];
            {
                int row = wm*16 + (lane & 15);
                int kb  = kc2 + ((lane >> 4) << 4);
                unsigned off = SWZ((unsigned)(row*128 + kb));
                LDSM4(ah[0], ah[1], ah[2], ah[3], aHb + off);
                LDSM4(al[0], al[1], al[2], al[3], aLb + off);
            }
            // hoist ALL B fragments for this K16 step
            unsigned bh[NF][2], bl[NF][2];
            #pragma unroll
            for (int g = 0; g < NF/2; g++) {
                int n  = wn*(NB/2) + g*16 + ((lane >> 4) << 3) + (lane & 7);
                int kb = kc2 + (((lane >> 3) & 1) << 4);
                unsigned off = SWZ((unsigned)(n*128 + kb));
                LDSM4(bh[2*g][0], bh[2*g][1], bh[2*g+1][0], bh[2*g+1][1], xHb + off);
                LDSM4(bl[2*g][0], bl[2*g][1], bl[2*g+1][0], bl[2*g+1][1], xLb + off);
            }
            // 3 sweeps over independent accumulators: RAW distance = NF
            #pragma unroll
            for (int nf = 0; nf < NF; nf++) MMA16816(acc[nf], ah, bh[nf]);
            #pragma unroll
            for (int nf = 0; nf < NF; nf++) MMA16816(acc[nf], ah, bl[nf]);
            #pragma unroll
            for (int nf = 0; nf < NF; nf++) MMA16816(acc[nf], al, bh[nf]);
        }
        __syncthreads();
    }

    // ---------------- epilogue ----------------
    const int gid = lane >> 2, tig = lane & 3;
    const int r = r0 + wm*16 + gid;
    float* O;
    int stride;
    if (MODE == 0)      { O = g_P[y]; stride = DD; }
    else if (MODE == 1) { O = g_B[y]; stride = DD; }
    else                { O = g_E[y]; stride = EMBD; }
    #pragma unroll
    for (int nf = 0; nf < NF; nf++) {
        int cc = wn*(NB/2) + nf*8 + 2*tig;
        *(float2*)&O[(size_t)r*stride + cc]     = make_float2(acc[nf][0], acc[nf][1]);
        *(float2*)&O[(size_t)(r+8)*stride + cc] = make_float2(acc[nf][2], acc[nf][3]);
    }
}

// ---------------- small fused projections ----------------
__global__ __launch_bounds__(256) void zd_kernel(const float* __restrict__ W)
{
    __shared__ float As [32][128];
    __shared__ float B0s[32][128];
    __shared__ float B1s[32][128];

    const int t  = threadIdx.x;
    const int e  = t & 63;
    const int ry = t >> 6;
    const int r0 = blockIdx.x * 32;

    #pragma unroll
    for (int i = 0; i < 4; i++) {
        int f = t + i*256;
        int row = f >> 5, c4 = f & 31;
        *(float4*)&As [row][4*c4] = *(const float4*)&g_A   [(size_t)(r0+row)*DD + 4*c4];
        *(float4*)&B0s[row][4*c4] = *(const float4*)&g_B[0][(size_t)(r0+row)*DD + 4*c4];
        *(float4*)&B1s[row][4*c4] = *(const float4*)&g_B[1][(size_t)(r0+row)*DD + 4*c4];
    }
    __syncthreads();

    float accZ[8], accD0[8], accD1[8];
    #pragma unroll
    for (int s = 0; s < 8; s++) { accZ[s] = 0.f; accD0[s] = 0.f; accD1[s] = 0.f; }

    for (int f = 0; f < 128; f++) {
        float wz0 = W[( 0  + f)*64 + e];
        float wz1 = W[(128 + f)*64 + e];
        float wz2 = W[(256 + f)*64 + e];
        float w00 = W[(384 + f)*64 + e];
        float w01 = W[(512 + f)*64 + e];
        float w10 = W[(640 + f)*64 + e];
        float w11 = W[(768 + f)*64 + e];
        #pragma unroll
        for (int s = 0; s < 8; s++) {
            int r = ry + 4*s;
            float a  = As [r][f];
            float b0 = B0s[r][f];
            float b1 = B1s[r][f];
            accZ [s] += a*wz0 + b0*wz1 + b1*wz2;
            accD0[s] += b0*w00 + b1*w01;
            accD1[s] += b0*w10 + b1*w11;
        }
    }
    #pragma unroll
    for (int s = 0; s < 8; s++) {
        int r = r0 + ry + 4*s;
        float cn = (float)g_cnt[r];
        g_Z    [(size_t)r*EMBD + e] = accZ[s];
        g_Dk[0][(size_t)r*EMBD + e] = cn * accD0[s];
        g_Dk[1][(size_t)r*EMBD + e] = cn * accD1[s];
    }
}

__global__ void final_kernel(const int* __restrict__ n_id,
                             const float* __restrict__ b,
                             float* __restrict__ out)
{
    int idx = blockIdx.x*blockDim.x + threadIdx.x;
    int j = idx >> 6, e = idx & 63;
    size_t zr = (size_t)n_id[j]*EMBD + e;
    out[idx] = tanhf(g_Z[zr] + g_E[0][zr] + g_E[1][zr] + b[e]);
}

// ---------------- launch ----------------
extern "C" void kernel_launch(void* const* d_in, const int* in_sizes, int n_in,
                              void* d_out, int out_size)
{
    const float* x    = (const float*)d_in[0];
    const float* K    = (const float*)d_in[1];
    const float* L    = (const float*)d_in[2];
    const float* tau  = (const float*)d_in[3];
    const float* W    = (const float*)d_in[4];
    const float* b    = (const float*)d_in[5];
    const int*   n_id = (const int*)  d_in[6];
    float* out = (float*)d_out;

    const int SM128 = 32768 + 4*128*128;   // 98304
    const int SM64  = 32768 + 4*64*128;    // 65536
    cudaFuncSetAttribute(gemm_hmma<128,0>, cudaFuncAttributeMaxDynamicSharedMemorySize, SM128);
    cudaFuncSetAttribute(gemm_hmma<128,1>, cudaFuncAttributeMaxDynamicSharedMemorySize, SM128);
    cudaFuncSetAttribute(gemm_hmma<64,2>,  cudaFuncAttributeMaxDynamicSharedMemorySize, SM64);

    zero_cnt_kernel<<<NTOT/256, 256>>>();
    count_kernel   <<<NTOT/256, 256>>>(n_id);

    // x^T split, then partial L@x over K halves, then fused combine+Ac^T split
    tsplit<128,0><<<NTOT/64, 256>>>(x);
    gemm_hmma<128,0><<<dim3(NTOT/64, 2), 256, SM128>>>(L);
    combine_tsplit<<<NTOT/64, 256>>>(x, tau);

    // B_k = K[k] @ Ac
    gemm_hmma<128,1><<<dim3(NTOT/64, 2), 256, SM128>>>(K);

    // Z and D_k
    zd_kernel<<<NTOT/32, 256>>>(W);

    // Dk^T splits, then E_k = K[k] @ D_k
    tsplit<64,2><<<NTOT/64, 256>>>(nullptr);
    tsplit<64,3><<<NTOT/64, 256>>>(nullptr);
    gemm_hmma<64,2><<<dim3(NTOT/64, 2), 256, SM64>>>(K);

    final_kernel<<<(NTOT*EMBD)/256, 256>>>(n_id, b, out);
}

// round 9
// speedup vs baseline: 1.0255x; 1.0255x over previous
#include <cuda_runtime.h>
#include <math.h>

#define NTOT 8192
#define DD   128
#define EMBD 64

// ---------------- scratch (device globals; no allocations) ----------------
__device__ float g_A [NTOT*DD];
__device__ float g_P [2][NTOT*DD];     // K-split partials of L@x
__device__ float g_B [2][NTOT*DD];
__device__ float g_Dk[2][NTOT*EMBD];
__device__ float g_E [2][NTOT*EMBD];
__device__ float g_Z [NTOT*EMBD];
__device__ int   g_cnt[NTOT];

// transposed bf16 hi/lo operands (X^T layouts [C][NTOT], K-contiguous)
__device__ unsigned short g_xt_hi [DD*NTOT];
__device__ unsigned short g_xt_lo [DD*NTOT];
__device__ unsigned short g_act_hi[DD*NTOT];
__device__ unsigned short g_act_lo[DD*NTOT];
__device__ unsigned short g_dt_hi [2][EMBD*NTOT];
__device__ unsigned short g_dt_lo [2][EMBD*NTOT];

// ---------------- helpers ----------------
__device__ __forceinline__ unsigned smem_u32(const void* p) {
    unsigned a;
    asm("{ .reg .u64 t; cvta.to.shared.u64 t, %1; cvt.u32.u64 %0, t; }" : "=r"(a) : "l"(p));
    return a;
}
#define SWZ(o) ((o) ^ (((o) >> 3) & 0x70))

#define LDSM4(d0,d1,d2,d3,addr) \
    asm volatile("ldmatrix.sync.aligned.m8n8.x4.shared.b16 {%0,%1,%2,%3}, [%4];" \
        : "=r"(d0), "=r"(d1), "=r"(d2), "=r"(d3) : "r"(addr))

#define MMA16816(c, a, b) \
    asm volatile("mma.sync.aligned.m16n8k16.row.col.f32.bf16.bf16.f32 " \
        "{%0,%1,%2,%3},{%4,%5,%6,%7},{%8,%9},{%0,%1,%2,%3};" \
        : "+f"((c)[0]), "+f"((c)[1]), "+f"((c)[2]), "+f"((c)[3]) \
        : "r"((a)[0]), "r"((a)[1]), "r"((a)[2]), "r"((a)[3]), \
          "r"((b)[0]), "r"((b)[1]))

#define CP16(dst, src) \
    asm volatile("cp.async.cg.shared.global [%0], [%1], 16;" :: "r"(dst), "l"(src))
#define CP_COMMIT() asm volatile("cp.async.commit_group;" ::: "memory")
#define CP_WAIT0()  asm volatile("cp.async.wait_group 0;" ::: "memory")

// bf16 hi/lo split of a float pair: hi = truncation (PRMT), lo = rn(x - hi)
__device__ __forceinline__ void split2(float f0, float f1, unsigned& hi, unsigned& lo) {
    unsigned u0 = __float_as_uint(f0), u1 = __float_as_uint(f1);
    unsigned h;
    asm("prmt.b32 %0, %1, %2, 0x7632;" : "=r"(h) : "r"(u0), "r"(u1));
    float h0 = __uint_as_float(u0 & 0xFFFF0000u);
    float h1 = __uint_as_float(u1 & 0xFFFF0000u);
    float r0 = f0 - h0, r1 = f1 - h1;
    unsigned l;
    asm("cvt.rn.bf16x2.f32 %0, %1, %2;" : "=r"(l) : "f"(r1), "f"(r0));
    hi = h; lo = l;
}

// ---------------- tiny kernels ----------------
__global__ void zero_cnt_kernel() {
    g_cnt[blockIdx.x*blockDim.x + threadIdx.x] = 0;
}
__global__ void count_kernel(const int* __restrict__ n_id) {
    atomicAdd(&g_cnt[n_id[blockIdx.x*blockDim.x + threadIdx.x]], 1);
}

// ---------------- transpose + bf16-split: [NTOT][C] f32 -> [C][NTOT] hi/lo ----
// SRC: 0=x(param) 2=g_Dk[0] 3=g_Dk[1]
template<int C, int SRC>
__global__ __launch_bounds__(256) void tsplit(const float* __restrict__ xext)
{
    const float* in;
    unsigned short *hi, *lo;
    if (SRC == 0)      { in = xext;    hi = g_xt_hi;    lo = g_xt_lo; }
    else if (SRC == 2) { in = g_Dk[0]; hi = g_dt_hi[0]; lo = g_dt_lo[0]; }
    else               { in = g_Dk[1]; hi = g_dt_hi[1]; lo = g_dt_lo[1]; }

    __shared__ float tile[64][C + 4];
    const int t  = threadIdx.x;
    const int r0 = blockIdx.x * 64;
    constexpr int F4 = C / 4;
    #pragma unroll
    for (int i = 0; i < 64*F4/256; i++) {
        int u = t + i*256;
        int row = u / F4, c4 = u % F4;
        float4 v = *(const float4*)&in[(size_t)(r0+row)*C + c4*4];
        tile[row][c4*4+0] = v.x; tile[row][c4*4+1] = v.y;
        tile[row][c4*4+2] = v.z; tile[row][c4*4+3] = v.w;
    }
    __syncthreads();
    const int c = t % C, grp = t / C;
    constexpr int RP = 64 / (256 / C);
    #pragma unroll
    for (int i = 0; i < RP/2; i++) {
        int r = grp*RP + 2*i;
        unsigned h, l;
        split2(tile[r][c], tile[r+1][c], h, l);
        *(unsigned*)&hi[(size_t)c*NTOT + r0 + r] = h;
        *(unsigned*)&lo[(size_t)c*NTOT + r0 + r] = l;
    }
}

// ---- fused: A = x - tau*(P0+P1); write g_A; transpose-split cnt*A -> act ----
__global__ __launch_bounds__(256) void combine_tsplit(const float* __restrict__ x,
                                                      const float* __restrict__ taup)
{
    __shared__ float tile[64][DD + 4];
    const int t  = threadIdx.x;
    const int r0 = blockIdx.x * 64;
    const float tv = taup[0];
    #pragma unroll
    for (int i = 0; i < 8; i++) {
        int u = t + i*256;
        int row = u >> 5, c4 = u & 31;
        size_t o = (size_t)(r0+row)*DD + c4*4;
        float4 xv = *(const float4*)&x[o];
        float4 p0 = *(const float4*)&g_P[0][o];
        float4 p1 = *(const float4*)&g_P[1][o];
        float cn = (float)g_cnt[r0+row];
        float4 a;
        a.x = xv.x - tv*(p0.x + p1.x);
        a.y = xv.y - tv*(p0.y + p1.y);
        a.z = xv.z - tv*(p0.z + p1.z);
        a.w = xv.w - tv*(p0.w + p1.w);
        *(float4*)&g_A[o] = a;
        tile[row][c4*4+0] = cn*a.x; tile[row][c4*4+1] = cn*a.y;
        tile[row][c4*4+2] = cn*a.z; tile[row][c4*4+3] = cn*a.w;
    }
    __syncthreads();
    const int c = t & 127, grp = t >> 7;
    #pragma unroll
    for (int i = 0; i < 16; i++) {
        int r = grp*32 + 2*i;
        unsigned h, l;
        split2(tile[r][c], tile[r+1][c], h, l);
        *(unsigned*)&g_act_hi[(size_t)c*NTOT + r0 + r] = h;
        *(unsigned*)&g_act_lo[(size_t)c*NTOT + r0 + r] = l;
    }
}

// ---------------- HMMA GEMM: 64-row tiles, 2 CTAs/SM, 2x4 warp layout -------
// MODE 0: Mat=L, K-split y  -> g_P[y]  (NB=128, grid(128,2))
// MODE 1: Mat=K[y], X=Ac^T  -> g_B[y]  (NB=128, grid(128,2))
// MODE 2: Mat=K[y], X=Dk^T  -> g_E[y]  (NB=64,  grid(128,2))
template<int NB, int MODE>
__global__ __launch_bounds__(256, 2) void gemm_hmma(const float* __restrict__ Mb)
{
    extern __shared__ char smem[];
    constexpr int NF  = NB / 32;        // n-frags per warp (warp covers NB/4 cols)
    constexpr int XSZ = NB * 128;       // bytes per X half-tile, 128B rows
    constexpr int XU  = NB / 32;        // 16B cp.async per thread per X half
    constexpr int NC  = (MODE == 0) ? 64 : 128;

    const int t = threadIdx.x, lane = t & 31, w = t >> 5;
    const int wm = w & 1, wn = w >> 1;  // 2 x 4 layout: warp tile 32 rows x NB/4 cols
    const int r0 = blockIdx.x * 64;
    const int y  = blockIdx.y;
    const int kbase = (MODE == 0) ? (y << 12) : 0;

    const float* Mat = (MODE == 0) ? Mb : Mb + (size_t)y * NTOT * NTOT;
    const unsigned short *XH, *XL;
    if (MODE == 0)      { XH = g_xt_hi;    XL = g_xt_lo; }
    else if (MODE == 1) { XH = g_act_hi;   XL = g_act_lo; }
    else                { XH = g_dt_hi[y]; XL = g_dt_lo[y]; }

    const unsigned su = smem_u32(smem);
    // layout: stage s: A hi @ s*16384, A lo @ s*16384+8192 ; X @ 32768 + s*2*XSZ

    float acc[2][NF][4];
    #pragma unroll
    for (int mf = 0; mf < 2; mf++)
        #pragma unroll
        for (int nf = 0; nf < NF; nf++)
            #pragma unroll
            for (int j = 0; j < 4; j++) acc[mf][nf][j] = 0.f;

    float4 mv[4];

    auto LOADG = [&](int c) {
        const int k0 = kbase + c * 64;
        const int s  = c & 1;
        #pragma unroll
        for (int i = 0; i < 4; i++) {
            int u = t + (i << 8);
            mv[i] = *(const float4*)&Mat[(size_t)(r0 + (u >> 4))*NTOT + k0 + ((u & 15) << 2)];
        }
        const unsigned xHb = su + 32768 + s*2*XSZ;
        #pragma unroll
        for (int i = 0; i < XU; i++) {
            int u = t + (i << 8);
            unsigned off = SWZ((unsigned)((u >> 3)*128 + (u & 7)*16));
            size_t  o = (size_t)(u >> 3)*NTOT + k0 + ((u & 7) << 3);
            CP16(xHb + off,       (const void*)&XH[o]);
            CP16(xHb + XSZ + off, (const void*)&XL[o]);
        }
        CP_COMMIT();
    };

    LOADG(0);
    for (int c = 0; c < NC; c++) {
        const int s = c & 1;
        char* aH = smem + s*16384;
        char* aL = aH + 8192;
        // store Mat tile (fp32 -> bf16 hi/lo, swizzled 128B rows)
        #pragma unroll
        for (int i = 0; i < 4; i++) {
            int u = t + (i << 8);
            int row = u >> 4, c4 = u & 15;
            unsigned h0, l0, h1, l1;
            split2(mv[i].x, mv[i].y, h0, l0);
            split2(mv[i].z, mv[i].w, h1, l1);
            unsigned off = SWZ((unsigned)(row*128 + c4*8));
            *(uint2*)(aH + off) = make_uint2(h0, h1);
            *(uint2*)(aL + off) = make_uint2(l0, l1);
        }
        CP_WAIT0();
        __syncthreads();          // single barrier per chunk

        if (c + 1 < NC) LOADG(c + 1);

        const unsigned aHb = su + s*16384;
        const unsigned aLb = aHb + 8192;
        const unsigned xHb = su + 32768 + s*2*XSZ;
        const unsigned xLb = xHb + XSZ;

        #pragma unroll
        for (int kk = 0; kk < 4; kk++) {
            const int kc2 = kk * 32;
            unsigned ah[2][4], al[2][4];
            #pragma unroll
            for (int mf = 0; mf < 2; mf++) {
                int row = wm*32 + mf*16 + (lane & 15);
                int kb  = kc2 + ((lane >> 4) << 4);
                unsigned off = SWZ((unsigned)(row*128 + kb));
                LDSM4(ah[mf][0], ah[mf][1], ah[mf][2], ah[mf][3], aHb + off);
                LDSM4(al[mf][0], al[mf][1], al[mf][2], al[mf][3], aLb + off);
            }
            unsigned bh[NF][2], bl[NF][2];
            #pragma unroll
            for (int g = 0; g < NF/2; g++) {
                int n  = wn*(NB/4) + g*16 + ((lane >> 4) << 3) + (lane & 7);
                int kb = kc2 + (((lane >> 3) & 1) << 4);
                unsigned off = SWZ((unsigned)(n*128 + kb));
                LDSM4(bh[2*g][0], bh[2*g][1], bh[2*g+1][0], bh[2*g+1][1], xHb + off);
                LDSM4(bl[2*g][0], bl[2*g][1], bl[2*g+1][0], bl[2*g+1][1], xLb + off);
            }
            #pragma unroll
            for (int nf = 0; nf < NF; nf++)
                #pragma unroll
                for (int mf = 0; mf < 2; mf++) MMA16816(acc[mf][nf], ah[mf], bh[nf]);
            #pragma unroll
            for (int nf = 0; nf < NF; nf++)
                #pragma unroll
                for (int mf = 0; mf < 2; mf++) MMA16816(acc[mf][nf], ah[mf], bl[nf]);
            #pragma unroll
            for (int nf = 0; nf < NF; nf++)
                #pragma unroll
                for (int mf = 0; mf < 2; mf++) MMA16816(acc[mf][nf], al[mf], bh[nf]);
        }
        // no second barrier: next chunk's stores target the other stage;
        // WAR on this stage is separated by the next iteration's barrier.
    }

    // ---------------- epilogue ----------------
    const int gid = lane >> 2, tig = lane & 3;
    float* O;
    int stride;
    if (MODE == 0)      { O = g_P[y]; stride = DD; }
    else if (MODE == 1) { O = g_B[y]; stride = DD; }
    else                { O = g_E[y]; stride = EMBD; }
    #pragma unroll
    for (int mf = 0; mf < 2; mf++) {
        int r = r0 + wm*32 + mf*16 + gid;
        #pragma unroll
        for (int nf = 0; nf < NF; nf++) {
            int cc = wn*(NB/4) + nf*8 + 2*tig;
            *(float2*)&O[(size_t)r*stride + cc]     = make_float2(acc[mf][nf][0], acc[mf][nf][1]);
            *(float2*)&O[(size_t)(r+8)*stride + cc] = make_float2(acc[mf][nf][2], acc[mf][nf][3]);
        }
    }
}

// ---------------- small fused projections ----------------
__global__ __launch_bounds__(256) void zd_kernel(const float* __restrict__ W)
{
    __shared__ float As [32][128];
    __shared__ float B0s[32][128];
    __shared__ float B1s[32][128];

    const int t  = threadIdx.x;
    const int e  = t & 63;
    const int ry = t >> 6;
    const int r0 = blockIdx.x * 32;

    #pragma unroll
    for (int i = 0; i < 4; i++) {
        int f = t + i*256;
        int row = f >> 5, c4 = f & 31;
        *(float4*)&As [row][4*c4] = *(const float4*)&g_A   [(size_t)(r0+row)*DD + 4*c4];
        *(float4*)&B0s[row][4*c4] = *(const float4*)&g_B[0][(size_t)(r0+row)*DD + 4*c4];
        *(float4*)&B1s[row][4*c4] = *(const float4*)&g_B[1][(size_t)(r0+row)*DD + 4*c4];
    }
    __syncthreads();

    float accZ[8], accD0[8], accD1[8];
    #pragma unroll
    for (int s = 0; s < 8; s++) { accZ[s] = 0.f; accD0[s] = 0.f; accD1[s] = 0.f; }

    for (int f = 0; f < 128; f++) {
        float wz0 = W[( 0  + f)*64 + e];
        float wz1 = W[(128 + f)*64 + e];
        float wz2 = W[(256 + f)*64 + e];
        float w00 = W[(384 + f)*64 + e];
        float w01 = W[(512 + f)*64 + e];
        float w10 = W[(640 + f)*64 + e];
        float w11 = W[(768 + f)*64 + e];
        #pragma unroll
        for (int s = 0; s < 8; s++) {
            int r = ry + 4*s;
            float a  = As [r][f];
            float b0 = B0s[r][f];
            float b1 = B1s[r][f];
            accZ [s] += a*wz0 + b0*wz1 + b1*wz2;
            accD0[s] += b0*w00 + b1*w01;
            accD1[s] += b0*w10 + b1*w11;
        }
    }
    #pragma unroll
    for (int s = 0; s < 8; s++) {
        int r = r0 + ry + 4*s;
        float cn = (float)g_cnt[r];
        g_Z    [(size_t)r*EMBD + e] = accZ[s];
        g_Dk[0][(size_t)r*EMBD + e] = cn * accD0[s];
        g_Dk[1][(size_t)r*EMBD + e] = cn * accD1[s];
    }
}

__global__ void final_kernel(const int* __restrict__ n_id,
                             const float* __restrict__ b,
                             float* __restrict__ out)
{
    int idx = blockIdx.x*blockDim.x + threadIdx.x;
    int j = idx >> 6, e = idx & 63;
    size_t zr = (size_t)n_id[j]*EMBD + e;
    out[idx] = tanhf(g_Z[zr] + g_E[0][zr] + g_E[1][zr] + b[e]);
}

// ---------------- launch ----------------
extern "C" void kernel_launch(void* const* d_in, const int* in_sizes, int n_in,
                              void* d_out, int out_size)
{
    const float* x    = (const float*)d_in[0];
    const float* K    = (const float*)d_in[1];
    const float* L    = (const float*)d_in[2];
    const float* tau  = (const float*)d_in[3];
    const float* W    = (const float*)d_in[4];
    const float* b    = (const float*)d_in[5];
    const int*   n_id = (const int*)  d_in[6];
    float* out = (float*)d_out;

    const int SM128 = 32768 + 4*128*128;   // 98304
    const int SM64  = 32768 + 4*64*128;    // 65536
    cudaFuncSetAttribute(gemm_hmma<128,0>, cudaFuncAttributeMaxDynamicSharedMemorySize, SM128);
    cudaFuncSetAttribute(gemm_hmma<128,1>, cudaFuncAttributeMaxDynamicSharedMemorySize, SM128);
    cudaFuncSetAttribute(gemm_hmma<64,2>,  cudaFuncAttributeMaxDynamicSharedMemorySize, SM64);

    zero_cnt_kernel<<<NTOT/256, 256>>>();
    count_kernel   <<<NTOT/256, 256>>>(n_id);

    // x^T split, then partial L@x over K halves, then fused combine+Ac^T split
    tsplit<128,0><<<NTOT/64, 256>>>(x);
    gemm_hmma<128,0><<<dim3(NTOT/64, 2), 256, SM128>>>(L);
    combine_tsplit<<<NTOT/64, 256>>>(x, tau);

    // B_k = K[k] @ Ac
    gemm_hmma<128,1><<<dim3(NTOT/64, 2), 256, SM128>>>(K);

    // Z and D_k
    zd_kernel<<<NTOT/32, 256>>>(W);

    // Dk^T splits, then E_k = K[k] @ D_k
    tsplit<64,2><<<NTOT/64, 256>>>(nullptr);
    tsplit<64,3><<<NTOT/64, 256>>>(nullptr);
    gemm_hmma<64,2><<<dim3(NTOT/64, 2), 256, SM64>>>(K);

    final_kernel<<<(NTOT*EMBD)/256, 256>>>(n_id, b, out);
}